// round 11
// baseline (speedup 1.0000x reference)
#include <cuda_runtime.h>
#include <cuda_bf16.h>
#include <math.h>

typedef unsigned long long u64;
#define M_TOTAL 32768
#define D_MODEL 1024
#define HALF 32
#define T_SEQ 8192
#define TAPS 32

__device__ float g_xp[M_TOTAL * HALF];
__device__ float g_y[M_TOTAL * HALF];
__device__ u64   g_Kp[TAPS * 16];

__device__ __forceinline__ u64 fma2(u64 a, u64 b, u64 c) {
    u64 d; asm("fma.rn.f32x2 %0, %1, %2, %3;" : "=l"(d) : "l"(a), "l"(b), "l"(c)); return d;
}
__device__ __forceinline__ u64 pack2(float lo, float hi) {
    u64 r; asm("mov.b64 %0, {%1, %2};" : "=l"(r) : "f"(lo), "f"(hi)); return r;
}
__device__ __forceinline__ float2 unpack2(u64 v) {
    float2 f; asm("mov.b64 {%0, %1}, %2;" : "=f"(f.x), "=f"(f.y) : "l"(v)); return f;
}

// FIR taps (proven): K[n,s] = exp(gain_n - tau*dt*s) * cos(s*angle_n).
__global__ void k_prep(const float* __restrict__ log_tau, const float* __restrict__ freq,
                       const float* __restrict__ Bp, const float* __restrict__ Cp,
                       const float* __restrict__ log_dt) {
    int tid = threadIdx.x, s = tid >> 4, np = tid & 15;
    double dt = exp((double)log_dt[0]);
    float k[2];
#pragma unroll
    for (int j = 0; j < 2; j++) {
        int n = np * 2 + j;
        double tau   = fmax(exp((double)log_tau[n]), 1e-4);
        double angle = (double)freq[n] * dt;
        double gain  = log(fabs((double)Bp[n]) + 1e-9) + log(fabs((double)Cp[n]) + 1e-9);
        k[j] = (float)(exp(gain - tau * dt * (double)s) * cos((double)s * angle));
    }
    g_Kp[s * 16 + np] = pack2(k[0], k[1]);
}

// GEMM1: xp[m,n] = sum_d x[m,d]*Win[n,d].
// Block 128 thr, tile 128 rows x 32 modes, grid 256.
// Thread = 4 rows (2 rowpairs via one dense LDS.128) x 8 modes (wdup broadcast).
// Inner: 1 LDS.128 + 4 LDS.128(bcast) + 16 fma2 per k-step. No pack2 in loop.
__global__ __launch_bounds__(128)
void k_proj(const float* __restrict__ x, const float* __restrict__ Win) {
    __shared__ float xs[32][132];    // [k][row]
    __shared__ u64   wdup[32][34];   // [k][mode] duplicated (w,w)
    const int tid = threadIdx.x, m0 = blockIdx.x * 128;
    const int lane = tid & 31;
    const int mg = tid >> 5;                  // warp id 0..3 -> modes mg*8..+7
    const int wn = tid >> 2, wqh = tid & 3;   // W loader: mode wn, half wqh

    float4 px[8];                             // this thread's row = tid, one chunk
    float4 pw0, pw1;
    const float* xrow = x + (size_t)(m0 + tid) * D_MODEL;
#pragma unroll
    for (int i = 0; i < 8; i++) px[i] = *(const float4*)(xrow + i * 4);
    pw0 = *(const float4*)(Win + (size_t)wn * D_MODEL + wqh * 8);
    pw1 = *(const float4*)(Win + (size_t)wn * D_MODEL + wqh * 8 + 4);

    u64 acc[2][8];
#pragma unroll
    for (int rp = 0; rp < 2; rp++)
#pragma unroll
        for (int m = 0; m < 8; m++) acc[rp][m] = 0ull;

#pragma unroll 1
    for (int c = 0; c < 32; c++) {
        __syncthreads();
#pragma unroll
        for (int i = 0; i < 8; i++) {         // transpose row tid into xs
            xs[i * 4 + 0][tid] = px[i].x;
            xs[i * 4 + 1][tid] = px[i].y;
            xs[i * 4 + 2][tid] = px[i].z;
            xs[i * 4 + 3][tid] = px[i].w;
        }
        {
            const float wv[8] = {pw0.x, pw0.y, pw0.z, pw0.w, pw1.x, pw1.y, pw1.z, pw1.w};
#pragma unroll
            for (int e = 0; e < 8; e++)
                wdup[wqh * 8 + e][wn] = pack2(wv[e], wv[e]);
        }
        __syncthreads();
        if (c < 31) {
            const int dc = (c + 1) * 32;
#pragma unroll
            for (int i = 0; i < 8; i++) px[i] = *(const float4*)(xrow + dc + i * 4);
            pw0 = *(const float4*)(Win + (size_t)wn * D_MODEL + dc + wqh * 8);
            pw1 = *(const float4*)(Win + (size_t)wn * D_MODEL + dc + wqh * 8 + 4);
        }
#pragma unroll
        for (int kk = 0; kk < 32; kk++) {
            ulonglong2 xv = *(const ulonglong2*)&xs[kk][lane * 4];   // rows lane*4..+3, dense
#pragma unroll
            for (int mp = 0; mp < 4; mp++) {
                ulonglong2 wv = *(const ulonglong2*)&wdup[kk][mg * 8 + mp * 2]; // bcast
                acc[0][mp * 2 + 0] = fma2(xv.x, wv.x, acc[0][mp * 2 + 0]);
                acc[0][mp * 2 + 1] = fma2(xv.x, wv.y, acc[0][mp * 2 + 1]);
                acc[1][mp * 2 + 0] = fma2(xv.y, wv.x, acc[1][mp * 2 + 0]);
                acc[1][mp * 2 + 1] = fma2(xv.y, wv.y, acc[1][mp * 2 + 1]);
            }
        }
    }
    // acc[rp][m] = (y[r_{2rp}][m], y[r_{2rp+1}][m]); rows lane*4..+3
#pragma unroll
    for (int r = 0; r < 4; r++) {
        const int rp = r >> 1, hi = r & 1;
        float v[8];
#pragma unroll
        for (int m = 0; m < 8; m++) {
            float2 f = unpack2(acc[rp][m]);
            v[m] = hi ? f.y : f.x;
        }
        float* dst = g_xp + (size_t)(m0 + lane * 4 + r) * HALF + mg * 8;
        *(float4*)dst       = make_float4(v[0], v[1], v[2], v[3]);
        *(float4*)(dst + 4) = make_float4(v[4], v[5], v[6], v[7]);
    }
}

// FIR (proven logic; grid doubled): 32-tap causal conv, 16 t's per slot.
__global__ __launch_bounds__(128)
void k_fir() {
    const int tid = threadIdx.x, np = tid & 15, slot = tid >> 4;
    const int m0 = blockIdx.x * 128 + slot * 16;
    const int t0 = m0 & (T_SEQ - 1);
    const u64* xp2 = (const u64*)g_xp;
    u64* y2 = (u64*)g_y;
    u64 K[TAPS], w[TAPS];
#pragma unroll
    for (int s = 0; s < TAPS; s++) K[s] = g_Kp[s * 16 + np];
#pragma unroll
    for (int s = 1; s < TAPS; s++) {
        u64 v = 0ull;
        if (t0 >= s) v = xp2[(size_t)(m0 - s) * 16 + np];
        w[(TAPS - s) & (TAPS - 1)] = v;
    }
#pragma unroll
    for (int tt = 0; tt < 16; tt++) {
        w[tt & (TAPS - 1)] = xp2[(size_t)(m0 + tt) * 16 + np];
        u64 acc = 0ull;
#pragma unroll
        for (int s = 0; s < TAPS; s++)
            acc = fma2(K[s], w[(tt - s) & (TAPS - 1)], acc);
        y2[(size_t)(m0 + tt) * 16 + np] = acc;
    }
}

// GEMM2: out[m,d] = sum_n y[m,n]*Wout[d,n].
// Block 128 thr (4 warps), tile 64 rows x 128 cols, grid (512, 8).
// Warp = 16 rows x 128 cols; thread = 16 rows (ydup bcast) x 4 cols (dense, colpairs).
// Inner per n: 1 LDS.128 + 8 LDS.128(bcast) + 32 fma2. No pack2 in loop.
__global__ __launch_bounds__(128)
void k_out(const float* __restrict__ Wo, float* __restrict__ out) {
    __shared__ u64   ydup[32][66];   // [n][row] duplicated (y,y)
    __shared__ float ws[32][132];    // [n][col]
    const int tid = threadIdx.x;
    const int m0 = blockIdx.x * 64, c0 = blockIdx.y * 128;
    const int wid = tid >> 5, lane = tid & 31;

    {   // y tile: 64 rows x 32 n  -> ydup
        const int row = tid >> 1, q = tid & 1;
        const float* src = g_y + (size_t)(m0 + row) * HALF + q * 16;
#pragma unroll
        for (int j = 0; j < 4; j++) {
            float4 v = *(const float4*)(src + j * 4);
            const int nb = q * 16 + j * 4;
            ydup[nb + 0][row] = pack2(v.x, v.x);
            ydup[nb + 1][row] = pack2(v.y, v.y);
            ydup[nb + 2][row] = pack2(v.z, v.z);
            ydup[nb + 3][row] = pack2(v.w, v.w);
        }
    }
    {   // Wo tile: 128 cols x 32 n, transposed
        const float* src = Wo + (size_t)(c0 + tid) * HALF;
#pragma unroll
        for (int q = 0; q < 8; q++) {
            float4 v = *(const float4*)(src + q * 4);
            ws[q * 4 + 0][tid] = v.x;
            ws[q * 4 + 1][tid] = v.y;
            ws[q * 4 + 2][tid] = v.z;
            ws[q * 4 + 3][tid] = v.w;
        }
    }
    __syncthreads();

    const int r0 = wid * 16;        // 16 rows per warp (uniform)
    u64 acc[16][2];
#pragma unroll
    for (int r = 0; r < 16; r++) { acc[r][0] = 0ull; acc[r][1] = 0ull; }

#pragma unroll 8
    for (int n = 0; n < 32; n++) {
        ulonglong2 wv = *(const ulonglong2*)&ws[n][lane * 4];   // 2 colpairs, dense
#pragma unroll
        for (int j = 0; j < 8; j++) {
            ulonglong2 yv = *(const ulonglong2*)&ydup[n][r0 + j * 2];  // bcast, 2 rows
            acc[j * 2 + 0][0] = fma2(yv.x, wv.x, acc[j * 2 + 0][0]);
            acc[j * 2 + 0][1] = fma2(yv.x, wv.y, acc[j * 2 + 0][1]);
            acc[j * 2 + 1][0] = fma2(yv.y, wv.x, acc[j * 2 + 1][0]);
            acc[j * 2 + 1][1] = fma2(yv.y, wv.y, acc[j * 2 + 1][1]);
        }
    }
#pragma unroll
    for (int r = 0; r < 16; r++) {
        float* dst = out + (size_t)(m0 + r0 + r) * D_MODEL + c0 + lane * 4;
        *(ulonglong2*)dst = make_ulonglong2(acc[r][0], acc[r][1]);
    }
}

extern "C" void kernel_launch(void* const* d_in, const int* in_sizes, int n_in,
                              void* d_out, int out_size) {
    const float* x       = (const float*)d_in[0];
    const float* log_tau = (const float*)d_in[1];
    const float* freq    = (const float*)d_in[2];
    const float* Bp      = (const float*)d_in[3];
    const float* Cp      = (const float*)d_in[4];
    const float* log_dt  = (const float*)d_in[5];
    const float* W_in    = (const float*)d_in[6];
    const float* W_out   = (const float*)d_in[7];
    float* out = (float*)d_out;

    k_prep<<<1, 512>>>(log_tau, freq, Bp, Cp, log_dt);
    k_proj<<<M_TOTAL / 128, 128>>>(x, W_in);
    k_fir<<<M_TOTAL / 128, 128>>>();
    k_out<<<dim3(M_TOTAL / 64, D_MODEL / 128), 128>>>(W_out, out);
}

// round 16
// speedup vs baseline: 1.1482x; 1.1482x over previous
#include <cuda_runtime.h>
#include <cuda_bf16.h>
#include <math.h>

typedef unsigned long long u64;
#define M_TOTAL 32768
#define D_MODEL 1024
#define HALF 32
#define T_SEQ 8192
#define TAPS 32

__device__ float g_xp[M_TOTAL * HALF];
__device__ float g_y[M_TOTAL * HALF];
__device__ u64   g_Kp[TAPS * 16];

__device__ __forceinline__ u64 fma2(u64 a, u64 b, u64 c) {
    u64 d; asm("fma.rn.f32x2 %0, %1, %2, %3;" : "=l"(d) : "l"(a), "l"(b), "l"(c)); return d;
}
__device__ __forceinline__ u64 pack2(float lo, float hi) {
    u64 r; asm("mov.b64 %0, {%1, %2};" : "=l"(r) : "f"(lo), "f"(hi)); return r;
}
__device__ __forceinline__ float2 unpack2(u64 v) {
    float2 f; asm("mov.b64 {%0, %1}, %2;" : "=f"(f.x), "=f"(f.y) : "l"(v)); return f;
}

// FIR taps (proven): K[n,s] = exp(gain_n - tau*dt*s) * cos(s*angle_n).
__global__ void k_prep(const float* __restrict__ log_tau, const float* __restrict__ freq,
                       const float* __restrict__ Bp, const float* __restrict__ Cp,
                       const float* __restrict__ log_dt) {
    int tid = threadIdx.x, s = tid >> 4, np = tid & 15;
    double dt = exp((double)log_dt[0]);
    float k[2];
#pragma unroll
    for (int j = 0; j < 2; j++) {
        int n = np * 2 + j;
        double tau   = fmax(exp((double)log_tau[n]), 1e-4);
        double angle = (double)freq[n] * dt;
        double gain  = log(fabs((double)Bp[n]) + 1e-9) + log(fabs((double)Cp[n]) + 1e-9);
        k[j] = (float)(exp(gain - tau * dt * (double)s) * cos((double)s * angle));
    }
    g_Kp[s * 16 + np] = pack2(k[0], k[1]);
}

// GEMM1: xp[m,n] = sum_d x[m,d]*Win[n,d].
// Block 128 thr (4 warps), tile 128 rows x 32 modes, grid 256, K-chunks of 32.
// Thread = 16 rows (8 rowpairs from xs, dedup LDS) x 2 modes (wdup).
// Inner per k: 4 LDS.128 + 1 LDS.128 + 16 fma2.
__global__ __launch_bounds__(128)
void k_proj(const float* __restrict__ x, const float* __restrict__ Win) {
    __shared__ float xs[32][132];    // [k][row], non-dup; rowpairs read as u64
    __shared__ u64   wdup[32][34];   // [k][mode] duplicated (w,w)
    const int tid = threadIdx.x, m0 = blockIdx.x * 128;
    const int wid = tid >> 5, lane = tid & 31;
    const int rgrp = lane >> 4, mgrp = lane & 15;
    const int r0 = wid * 32 + rgrp * 16;      // 16 rows
    const int mm = mgrp * 2;                  // 2 modes
    const int lrow = tid >> 3, lq = tid & 7;  // x loader: rows lrow+16i, k-quad lq
    const int wmode = tid >> 2, wq = tid & 3; // W loader

    const float* xr = x + (size_t)(m0 + lrow) * D_MODEL + lq * 4;
    const float* wr = Win + (size_t)wmode * D_MODEL + wq * 8;
    float4 px[8], pw0, pw1;
#pragma unroll
    for (int i = 0; i < 8; i++)
        px[i] = *(const float4*)(xr + (size_t)(16 * i) * D_MODEL);
    pw0 = *(const float4*)wr;
    pw1 = *(const float4*)(wr + 4);

    u64 acc[8][2];
#pragma unroll
    for (int rp = 0; rp < 8; rp++) { acc[rp][0] = 0ull; acc[rp][1] = 0ull; }

#pragma unroll 1
    for (int c = 0; c < 32; c++) {
        __syncthreads();
#pragma unroll
        for (int i = 0; i < 8; i++) {         // row lrow+16i, k = lq*4+e
            const int row = lrow + 16 * i;
            xs[lq * 4 + 0][row] = px[i].x;
            xs[lq * 4 + 1][row] = px[i].y;
            xs[lq * 4 + 2][row] = px[i].z;
            xs[lq * 4 + 3][row] = px[i].w;
        }
        {
            const float wv[8] = {pw0.x, pw0.y, pw0.z, pw0.w, pw1.x, pw1.y, pw1.z, pw1.w};
#pragma unroll
            for (int e = 0; e < 8; e++)
                wdup[wq * 8 + e][wmode] = pack2(wv[e], wv[e]);
        }
        __syncthreads();
        if (c < 31) {
            const int dc = (c + 1) * 32;
#pragma unroll
            for (int i = 0; i < 8; i++)
                px[i] = *(const float4*)(xr + dc + (size_t)(16 * i) * D_MODEL);
            pw0 = *(const float4*)(wr + dc);
            pw1 = *(const float4*)(wr + dc + 4);
        }
#pragma unroll
        for (int kk = 0; kk < 32; kk++) {
            ulonglong2 xv0 = *(const ulonglong2*)&xs[kk][r0];       // rowpairs 0,1
            ulonglong2 xv1 = *(const ulonglong2*)&xs[kk][r0 + 4];   // 2,3
            ulonglong2 xv2 = *(const ulonglong2*)&xs[kk][r0 + 8];   // 4,5
            ulonglong2 xv3 = *(const ulonglong2*)&xs[kk][r0 + 12];  // 6,7
            ulonglong2 wv  = *(const ulonglong2*)&wdup[kk][mm];     // 2 modes (dup)
            u64 xp_[8] = {xv0.x, xv0.y, xv1.x, xv1.y, xv2.x, xv2.y, xv3.x, xv3.y};
#pragma unroll
            for (int rp = 0; rp < 8; rp++) {
                acc[rp][0] = fma2(xp_[rp], wv.x, acc[rp][0]);
                acc[rp][1] = fma2(xp_[rp], wv.y, acc[rp][1]);
            }
        }
    }
    // acc[rp][j]: lo = xp[r0+2rp][mm+j], hi = xp[r0+2rp+1][mm+j]
#pragma unroll
    for (int rp = 0; rp < 8; rp++) {
        float2 a0 = unpack2(acc[rp][0]);
        float2 a1 = unpack2(acc[rp][1]);
        float* d0 = g_xp + (size_t)(m0 + r0 + rp * 2) * HALF + mm;
        *(float2*)d0          = make_float2(a0.x, a1.x);
        *(float2*)(d0 + HALF) = make_float2(a0.y, a1.y);
    }
}

// FIR (proven): 32-tap causal conv, 16 t's per slot, grid 256.
__global__ __launch_bounds__(128)
void k_fir() {
    const int tid = threadIdx.x, np = tid & 15, slot = tid >> 4;
    const int m0 = blockIdx.x * 128 + slot * 16;
    const int t0 = m0 & (T_SEQ - 1);
    const u64* xp2 = (const u64*)g_xp;
    u64* y2 = (u64*)g_y;
    u64 K[TAPS], w[TAPS];
#pragma unroll
    for (int s = 0; s < TAPS; s++) K[s] = g_Kp[s * 16 + np];
#pragma unroll
    for (int s = 1; s < TAPS; s++) {
        u64 v = 0ull;
        if (t0 >= s) v = xp2[(size_t)(m0 - s) * 16 + np];
        w[(TAPS - s) & (TAPS - 1)] = v;
    }
#pragma unroll
    for (int tt = 0; tt < 16; tt++) {
        w[tt & (TAPS - 1)] = xp2[(size_t)(m0 + tt) * 16 + np];
        u64 acc = 0ull;
#pragma unroll
        for (int s = 0; s < TAPS; s++)
            acc = fma2(K[s], w[(tt - s) & (TAPS - 1)], acc);
        y2[(size_t)(m0 + tt) * 16 + np] = acc;
    }
}

// GEMM2: out[m,d] = sum_n y[m,n]*Wout[d,n].
// Block 256 thr (8 warps), tile 128 rows x 128 cols, grid (256, 8).
// Thread = 16 rows (8 rowpairs, dedup LDS from ys) x 4 cols (wdup).
// Inner per n: 4 LDS.128 (y) + 2 LDS.128 (w) + 32 fma2.
__global__ __launch_bounds__(256)
void k_out(const float* __restrict__ Wo, float* __restrict__ out) {
    __shared__ float ys[32][132];    // [n][row], non-dup
    __shared__ u64   wdup[32][130];  // [n][col] duplicated (w,w)
    const int tid = threadIdx.x;
    const int m0 = blockIdx.x * 128, c0 = blockIdx.y * 128;
    const int wid = tid >> 5, lane = tid & 31;
    const int wr = wid >> 1, wc = wid & 1;
    const int rgrp = lane >> 4, cgrp = lane & 15;
    const int r0 = wr * 32 + rgrp * 16;        // 16 rows
    const int cl = wc * 64 + cgrp * 4;         // 4 cols

    {   // y tile: 128 rows x 32 n
        const int row = tid >> 1, h = tid & 1;
        const float* src = g_y + (size_t)(m0 + row) * HALF + h * 16;
#pragma unroll
        for (int i = 0; i < 4; i++) {
            float4 v = *(const float4*)(src + i * 4);
            ys[h * 16 + i * 4 + 0][row] = v.x;
            ys[h * 16 + i * 4 + 1][row] = v.y;
            ys[h * 16 + i * 4 + 2][row] = v.z;
            ys[h * 16 + i * 4 + 3][row] = v.w;
        }
    }
    {   // W tile: 128 cols x 32 n, dup'd
        const int col = tid >> 1, h = tid & 1;
        const float* src = Wo + (size_t)(c0 + col) * HALF + h * 16;
#pragma unroll
        for (int i = 0; i < 4; i++) {
            float4 v = *(const float4*)(src + i * 4);
            wdup[h * 16 + i * 4 + 0][col] = pack2(v.x, v.x);
            wdup[h * 16 + i * 4 + 1][col] = pack2(v.y, v.y);
            wdup[h * 16 + i * 4 + 2][col] = pack2(v.z, v.z);
            wdup[h * 16 + i * 4 + 3][col] = pack2(v.w, v.w);
        }
    }
    __syncthreads();

    u64 acc[8][4];
#pragma unroll
    for (int rp = 0; rp < 8; rp++)
#pragma unroll
        for (int cc = 0; cc < 4; cc++) acc[rp][cc] = 0ull;

#pragma unroll 4
    for (int n = 0; n < 32; n++) {
        ulonglong2 yv0 = *(const ulonglong2*)&ys[n][r0];
        ulonglong2 yv1 = *(const ulonglong2*)&ys[n][r0 + 4];
        ulonglong2 yv2 = *(const ulonglong2*)&ys[n][r0 + 8];
        ulonglong2 yv3 = *(const ulonglong2*)&ys[n][r0 + 12];
        ulonglong2 wv0 = *(const ulonglong2*)&wdup[n][cl];
        ulonglong2 wv1 = *(const ulonglong2*)&wdup[n][cl + 2];
        u64 yp[8] = {yv0.x, yv0.y, yv1.x, yv1.y, yv2.x, yv2.y, yv3.x, yv3.y};
        u64 wp[4] = {wv0.x, wv0.y, wv1.x, wv1.y};
#pragma unroll
        for (int rp = 0; rp < 8; rp++) {
            acc[rp][0] = fma2(yp[rp], wp[0], acc[rp][0]);
            acc[rp][1] = fma2(yp[rp], wp[1], acc[rp][1]);
            acc[rp][2] = fma2(yp[rp], wp[2], acc[rp][2]);
            acc[rp][3] = fma2(yp[rp], wp[3], acc[rp][3]);
        }
    }
    // acc[rp][cc]: lo = out[r0+2rp][cl+cc], hi = row+1
#pragma unroll
    for (int rp = 0; rp < 8; rp++) {
        float2 a0 = unpack2(acc[rp][0]);
        float2 a1 = unpack2(acc[rp][1]);
        float2 a2 = unpack2(acc[rp][2]);
        float2 a3 = unpack2(acc[rp][3]);
        float* d0 = out + (size_t)(m0 + r0 + rp * 2) * D_MODEL + c0 + cl;
        *(float4*)d0             = make_float4(a0.x, a1.x, a2.x, a3.x);
        *(float4*)(d0 + D_MODEL) = make_float4(a0.y, a1.y, a2.y, a3.y);
    }
}

extern "C" void kernel_launch(void* const* d_in, const int* in_sizes, int n_in,
                              void* d_out, int out_size) {
    const float* x       = (const float*)d_in[0];
    const float* log_tau = (const float*)d_in[1];
    const float* freq    = (const float*)d_in[2];
    const float* Bp      = (const float*)d_in[3];
    const float* Cp      = (const float*)d_in[4];
    const float* log_dt  = (const float*)d_in[5];
    const float* W_in    = (const float*)d_in[6];
    const float* W_out   = (const float*)d_in[7];
    float* out = (float*)d_out;

    k_prep<<<1, 512>>>(log_tau, freq, Bp, Cp, log_dt);
    k_proj<<<M_TOTAL / 128, 128>>>(x, W_in);
    k_fir<<<M_TOTAL / 128, 128>>>();
    k_out<<<dim3(M_TOTAL / 128, D_MODEL / 128), 256>>>(W_out, out);
}